// round 1
// baseline (speedup 1.0000x reference)
#include <cuda_runtime.h>
#include <cuda_bf16.h>
#include <cstdint>
#include <cstddef>

// Problem dims (hardcoded per reference)
#define BD 512      // batch
#define HD 1024     // hidden
#define OD 256      // output dim
#define TT 128      // target length
#define ND 4096     // 4*HD gate columns (interleaved i,f,g,o per unit)

// GEMM tile config
#define BM 128
#define BN 128
#define BK 32
#define SA_PITCH 36          // 128 x 36 floats per A stage (pad for conflict-free frag loads)
#define SB_PITCH 136         // 32 x 136 floats per B stage
#define SA_ELEMS (128 * SA_PITCH)
#define SB_ELEMS (32 * SB_PITCH)
#define SG_PITCH 132         // gates tile pitch in epilogue
#define SMEM_BYTES ((2 * SA_ELEMS + 2 * SB_ELEMS) * 4)   // 71680 B  (> 128*132*4 = 67584)

// ---------------- scratch (device globals; no runtime allocation) ----------------
__device__ __align__(16) float g_Wg0[(size_t)HD * ND];     // 16 MB  interleaved W_hh^T (tf32-rounded)
__device__ __align__(16) float g_Wg [(size_t)HD * ND];     // 16 MB  interleaved W_hh^T + (W_ih W_out)^T
__device__ __align__(16) float g_WihT[(size_t)OD * ND];    // 4 MB   interleaved W_ih^T (tf32)
__device__ __align__(16) float g_WoutT[(size_t)HD * OD];   // 1 MB   W_out^T (tf32)
__device__ __align__(16) float g_b0[ND];
__device__ __align__(16) float g_bg[ND];
__device__ __align__(16) float g_h0[(size_t)BD * HD];      // tf32-rounded encoder hidden
__device__ __align__(16) float g_c [(size_t)BD * HD];      // cell state (fp32)
__device__ __align__(16) float g_H [(size_t)TT * BD * HD]; // 256 MB: h after each step (tf32-rounded)

// ---------------- helpers ----------------
__device__ __forceinline__ float to_tf32(float x) {
    unsigned u;
    asm("cvt.rna.tf32.f32 %0, %1;" : "=r"(u) : "f"(x));
    return __uint_as_float(u);
}
__device__ __forceinline__ float fsigmoid(float x) { return 1.0f / (1.0f + __expf(-x)); }
__device__ __forceinline__ float ftanh(float x) {
    float e = __expf(2.0f * x);
    return 1.0f - 2.0f / (e + 1.0f);   // safe at +/-inf
}
__device__ __forceinline__ void cp_a16(float* d, const float* s) {
    unsigned a = (unsigned)__cvta_generic_to_shared(d);
    asm volatile("cp.async.cg.shared.global [%0], [%1], 16;" :: "r"(a), "l"(s));
}

// ---------------- shared tf32 mma mainloop: C(128x128) += A(128xK) * B(KxN tile) ----------------
__device__ __forceinline__ void gemm_tile(
    const float* __restrict__ A, int lda,
    const float* __restrict__ B, int ldb,
    int m0, int n0, int kTiles,
    float (&acc)[4][4][4], float* sm)
{
    float* sA = sm;                    // [2][128][SA_PITCH]
    float* sB = sm + 2 * SA_ELEMS;     // [2][32][SB_PITCH]
    const int tid = threadIdx.x;
    const int lane = tid & 31;
    const int wid = tid >> 5;
    const int wm = wid & 1, wn = wid >> 1;
    const int gid = lane >> 2, tig = lane & 3;

    // prologue: stage 0
    {
        #pragma unroll
        for (int it = 0; it < 4; ++it) {
            int slot = tid + it * 256;
            int r = slot >> 3, c4 = (slot & 7) << 2;
            cp_a16(sA + r * SA_PITCH + c4, A + (size_t)(m0 + r) * lda + c4);
        }
        #pragma unroll
        for (int it = 0; it < 4; ++it) {
            int slot = tid + it * 256;
            int r = slot >> 5, c4 = (slot & 31) << 2;
            cp_a16(sB + r * SB_PITCH + c4, B + (size_t)r * ldb + n0 + c4);
        }
        asm volatile("cp.async.commit_group;" ::: "memory");
    }

    for (int kt = 0; kt < kTiles; ++kt) {
        if (kt + 1 < kTiles) {
            const int k0 = (kt + 1) * BK;
            float* dA = sA + ((kt + 1) & 1) * SA_ELEMS;
            float* dB = sB + ((kt + 1) & 1) * SB_ELEMS;
            #pragma unroll
            for (int it = 0; it < 4; ++it) {
                int slot = tid + it * 256;
                int r = slot >> 3, c4 = (slot & 7) << 2;
                cp_a16(dA + r * SA_PITCH + c4, A + (size_t)(m0 + r) * lda + k0 + c4);
            }
            #pragma unroll
            for (int it = 0; it < 4; ++it) {
                int slot = tid + it * 256;
                int r = slot >> 5, c4 = (slot & 31) << 2;
                cp_a16(dB + r * SB_PITCH + c4, B + (size_t)(k0 + r) * ldb + n0 + c4);
            }
            asm volatile("cp.async.commit_group;" ::: "memory");
            asm volatile("cp.async.wait_group 1;" ::: "memory");
        } else {
            asm volatile("cp.async.wait_group 0;" ::: "memory");
        }
        __syncthreads();

        const float* cA = sA + (kt & 1) * SA_ELEMS;
        const float* cB = sB + (kt & 1) * SB_ELEMS;
        #pragma unroll
        for (int ks = 0; ks < 4; ++ks) {
            const int k = ks * 8;
            unsigned af[4][4], bfr[4][2];
            #pragma unroll
            for (int mf = 0; mf < 4; ++mf) {
                int r = wm * 64 + mf * 16 + gid;
                af[mf][0] = __float_as_uint(cA[r * SA_PITCH + k + tig]);
                af[mf][1] = __float_as_uint(cA[(r + 8) * SA_PITCH + k + tig]);
                af[mf][2] = __float_as_uint(cA[r * SA_PITCH + k + tig + 4]);
                af[mf][3] = __float_as_uint(cA[(r + 8) * SA_PITCH + k + tig + 4]);
            }
            #pragma unroll
            for (int nf = 0; nf < 4; ++nf) {
                int c = wn * 32 + nf * 8 + gid;
                bfr[nf][0] = __float_as_uint(cB[(k + tig) * SB_PITCH + c]);
                bfr[nf][1] = __float_as_uint(cB[(k + tig + 4) * SB_PITCH + c]);
            }
            #pragma unroll
            for (int mf = 0; mf < 4; ++mf)
                #pragma unroll
                for (int nf = 0; nf < 4; ++nf)
                    asm volatile(
                        "mma.sync.aligned.m16n8k8.row.col.f32.tf32.tf32.f32 "
                        "{%0,%1,%2,%3}, {%4,%5,%6,%7}, {%8,%9}, {%0,%1,%2,%3};"
                        : "+f"(acc[mf][nf][0]), "+f"(acc[mf][nf][1]),
                          "+f"(acc[mf][nf][2]), "+f"(acc[mf][nf][3])
                        : "r"(af[mf][0]), "r"(af[mf][1]), "r"(af[mf][2]), "r"(af[mf][3]),
                          "r"(bfr[nf][0]), "r"(bfr[nf][1]));
        }
        __syncthreads();
    }
}

// ---------------- setup kernels ----------------
// Interleaved column index: n = 4*j + g  <->  reference gate row n' = g*HD + j
__global__ void k_build_Wg0(const float* __restrict__ Whh) {
    size_t idx = (size_t)blockIdx.x * blockDim.x + threadIdx.x;
    if (idx >= (size_t)HD * ND) return;
    int k = (int)(idx >> 12);
    int n = (int)(idx & (ND - 1));
    int j = n >> 2, g = n & 3;
    g_Wg0[idx] = to_tf32(Whh[(size_t)(g * HD + j) * HD + k]);
}
__global__ void k_build_WihT(const float* __restrict__ Wih) {
    size_t idx = (size_t)blockIdx.x * blockDim.x + threadIdx.x;
    if (idx >= (size_t)OD * ND) return;
    int o = (int)(idx >> 12);
    int n = (int)(idx & (ND - 1));
    int j = n >> 2, g = n & 3;
    g_WihT[idx] = to_tf32(Wih[(size_t)(g * HD + j) * OD + o]);
}
__global__ void k_build_WoutT(const float* __restrict__ Wout) {
    size_t idx = (size_t)blockIdx.x * blockDim.x + threadIdx.x;
    if (idx >= (size_t)HD * OD) return;
    int k = (int)(idx >> 8);
    int o = (int)(idx & (OD - 1));
    g_WoutT[idx] = to_tf32(Wout[(size_t)o * HD + k]);
}
__global__ void k_bias(const float* __restrict__ Wih, const float* __restrict__ bih,
                       const float* __restrict__ bhh, const float* __restrict__ bout) {
    int n = blockIdx.x * blockDim.x + threadIdx.x;
    if (n >= ND) return;
    int j = n >> 2, g = n & 3;
    int np = g * HD + j;
    float b0 = bih[np] + bhh[np];
    float acc = 0.f;
    const float* wr = Wih + (size_t)np * OD;
    for (int o = 0; o < OD; ++o) acc += wr[o] * bout[o];
    g_b0[n] = b0;
    g_bg[n] = b0 + acc;
}
__global__ void k_h0c(const float* __restrict__ enc) {
    size_t idx = (size_t)blockIdx.x * blockDim.x + threadIdx.x;
    if (idx >= (size_t)BD * HD) return;
    g_h0[idx] = to_tf32(enc[idx]);
    g_c[idx] = 0.0f;
}
// Wg[k][n] = tf32( Wg0[k][n] + sum_o WoutT[k][o] * WihT[o][n] )
__global__ __launch_bounds__(256, 1) void k_build_Wg() {
    extern __shared__ float smem[];
    const int m0 = blockIdx.y * BM;   // k-dim of Wg (8 tiles)
    const int n0 = blockIdx.x * BN;   // 32 tiles
    float acc[4][4][4];
    #pragma unroll
    for (int a = 0; a < 4; ++a)
        #pragma unroll
        for (int b = 0; b < 4; ++b)
            #pragma unroll
            for (int c = 0; c < 4; ++c) acc[a][b][c] = 0.f;
    gemm_tile(g_WoutT, OD, g_WihT, ND, m0, n0, OD / BK, acc, smem);

    const int tid = threadIdx.x, lane = tid & 31, wid = tid >> 5;
    const int wm = wid & 1, wn = wid >> 1, gid = lane >> 2, tig = lane & 3;
    #pragma unroll
    for (int mf = 0; mf < 4; ++mf)
        #pragma unroll
        for (int nf = 0; nf < 4; ++nf) {
            int r = wm * 64 + mf * 16 + gid;
            int c = wn * 32 + nf * 8 + 2 * tig;
            size_t b0i = (size_t)(m0 + r) * ND + n0 + c;
            size_t b1i = (size_t)(m0 + r + 8) * ND + n0 + c;
            g_Wg[b0i]     = to_tf32(g_Wg0[b0i]     + acc[mf][nf][0]);
            g_Wg[b0i + 1] = to_tf32(g_Wg0[b0i + 1] + acc[mf][nf][1]);
            g_Wg[b1i]     = to_tf32(g_Wg0[b1i]     + acc[mf][nf][2]);
            g_Wg[b1i + 1] = to_tf32(g_Wg0[b1i + 1] + acc[mf][nf][3]);
        }
}

// ---------------- recurrence step ----------------
__global__ __launch_bounds__(256, 1) void k_step(int t) {
    extern __shared__ float smem[];
    const float* hprev = (t == 0) ? g_h0 : (g_H + (size_t)(t - 1) * BD * HD);
    const float* W     = (t == 0) ? g_Wg0 : g_Wg;
    const float* bias  = (t == 0) ? g_b0 : g_bg;
    float* hout = g_H + (size_t)t * BD * HD;

    const int ct = blockIdx.x;        // 0..31 gate-col tiles (32 hidden units each)
    const int bt = blockIdx.y;        // 0..3  batch tiles
    const int m0 = bt * BM, n0 = ct * BN;

    float acc[4][4][4];
    #pragma unroll
    for (int a = 0; a < 4; ++a)
        #pragma unroll
        for (int b = 0; b < 4; ++b)
            #pragma unroll
            for (int c = 0; c < 4; ++c) acc[a][b][c] = 0.f;
    gemm_tile(hprev, HD, W, ND, m0, n0, HD / BK, acc, smem);

    // stash gates to smem (interleaved i,f,g,o per unit)
    const int tid = threadIdx.x, lane = tid & 31, wid = tid >> 5;
    const int wm = wid & 1, wn = wid >> 1, gid = lane >> 2, tig = lane & 3;
    float* sG = smem;                 // [128][SG_PITCH]
    #pragma unroll
    for (int mf = 0; mf < 4; ++mf)
        #pragma unroll
        for (int nf = 0; nf < 4; ++nf) {
            int r = wm * 64 + mf * 16 + gid;
            int c = wn * 32 + nf * 8 + 2 * tig;
            sG[r * SG_PITCH + c]           = acc[mf][nf][0];
            sG[r * SG_PITCH + c + 1]       = acc[mf][nf][1];
            sG[(r + 8) * SG_PITCH + c]     = acc[mf][nf][2];
            sG[(r + 8) * SG_PITCH + c + 1] = acc[mf][nf][3];
        }
    __syncthreads();

    // LSTM cell: 128 rows x 32 units in this tile
    for (int i = tid; i < 128 * 32; i += 256) {
        int r = i >> 5, u = i & 31;
        int b = m0 + r;
        int j = ct * 32 + u;
        float4 gv = *(const float4*)&sG[r * SG_PITCH + 4 * u];
        float4 bb = *(const float4*)&bias[n0 + 4 * u];
        float ig = fsigmoid(gv.x + bb.x);
        float fg = fsigmoid(gv.y + bb.y);
        float gg = ftanh(gv.z + bb.z);
        float og = fsigmoid(gv.w + bb.w);
        size_t cidx = (size_t)b * HD + j;
        float cn = fg * g_c[cidx] + ig * gg;
        g_c[cidx] = cn;
        hout[cidx] = to_tf32(og * ftanh(cn));
    }
}

// ---------------- final prediction GEMM: (T*B, O) = H_all @ WoutT + b_out ----------------
__global__ __launch_bounds__(256, 1) void k_pred(const float* __restrict__ bout,
                                                 float* __restrict__ out) {
    extern __shared__ float smem[];
    const int m0 = blockIdx.y * BM;   // over T*B = 65536 rows (512 tiles)
    const int n0 = blockIdx.x * BN;   // 2 tiles of O=256
    float acc[4][4][4];
    #pragma unroll
    for (int a = 0; a < 4; ++a)
        #pragma unroll
        for (int b = 0; b < 4; ++b)
            #pragma unroll
            for (int c = 0; c < 4; ++c) acc[a][b][c] = 0.f;
    gemm_tile(g_H, HD, g_WoutT, OD, m0, n0, HD / BK, acc, smem);

    const int tid = threadIdx.x, lane = tid & 31, wid = tid >> 5;
    const int wm = wid & 1, wn = wid >> 1, gid = lane >> 2, tig = lane & 3;
    #pragma unroll
    for (int mf = 0; mf < 4; ++mf)
        #pragma unroll
        for (int nf = 0; nf < 4; ++nf) {
            int c = wn * 32 + nf * 8 + 2 * tig;
            int o = n0 + c;
            float b0v = bout[o], b1v = bout[o + 1];
            #pragma unroll
            for (int half = 0; half < 2; ++half) {
                int m = m0 + wm * 64 + mf * 16 + gid + half * 8;
                int t = m >> 9;          // m = t*512 + b
                int b = m & 511;
                float2 v;
                v.x = acc[mf][nf][half * 2 + 0] + b0v;
                v.y = acc[mf][nf][half * 2 + 1] + b1v;
                *(float2*)&out[((size_t)b * TT + t) * OD + o] = v;
            }
        }
}

// ---------------- host launcher ----------------
extern "C" void kernel_launch(void* const* d_in, const int* in_sizes, int n_in,
                              void* d_out, int out_size) {
    const float* enc  = (const float*)d_in[0];
    // d_in[1] = target_length (known: 128)
    const float* Wih  = (const float*)d_in[2];
    const float* Whh  = (const float*)d_in[3];
    const float* bih  = (const float*)d_in[4];
    const float* bhh  = (const float*)d_in[5];
    const float* Wout = (const float*)d_in[6];
    const float* bout = (const float*)d_in[7];
    float* out = (float*)d_out;

    cudaFuncSetAttribute(k_build_Wg, cudaFuncAttributeMaxDynamicSharedMemorySize, SMEM_BYTES);
    cudaFuncSetAttribute(k_step,     cudaFuncAttributeMaxDynamicSharedMemorySize, SMEM_BYTES);
    cudaFuncSetAttribute(k_pred,     cudaFuncAttributeMaxDynamicSharedMemorySize, SMEM_BYTES);

    k_build_Wg0 <<<(HD * ND + 255) / 256, 256>>>(Whh);
    k_build_WihT<<<(OD * ND + 255) / 256, 256>>>(Wih);
    k_build_WoutT<<<(HD * OD + 255) / 256, 256>>>(Wout);
    k_bias      <<<(ND + 255) / 256, 256>>>(Wih, bih, bhh, bout);
    k_h0c       <<<(BD * HD + 255) / 256, 256>>>(enc);

    {
        dim3 g(ND / BN, HD / BM);          // 32 x 8
        k_build_Wg<<<g, 256, SMEM_BYTES>>>();
    }
    {
        dim3 g(ND / BN, BD / BM);          // 32 x 4
        for (int t = 0; t < TT; ++t) k_step<<<g, 256, SMEM_BYTES>>>(t);
    }
    {
        dim3 g(OD / BN, (TT * BD) / BM);   // 2 x 512
        k_pred<<<g, 256, SMEM_BYTES>>>(bout, out);
    }
}

// round 6
// speedup vs baseline: 1.3395x; 1.3395x over previous
#include <cuda_runtime.h>
#include <cuda_bf16.h>
#include <cstdint>
#include <cstddef>

// Problem dims
#define BD 512      // batch
#define HD 1024     // hidden
#define OD 256      // output dim
#define TT 128      // target length
#define ND 4096     // 4*HD gate columns (blocked: col = (j>>3)*32 + gate*8 + (j&7))

// ---------------- mma.sync GEMM config (new vectorized-feed mainloop) ----------------
#define GP 36                       // smem pitch in floats (conflict-free for v4 frag loads)
#define GSTG (128 * GP)             // one stage of one operand: 128 rows x 36
#define GEMM_SMEM (3 * 2 * GSTG * 4)  // 3 stages x (A+B) = 110592 B

// ---------------- tcgen05 step kernel config (dormant unless arch-specific pass) ----
#define S_STAGES 4
#define STG_BYTES 16384             // 128 rows x 128B
#define OFF_TMEMPTR 0
#define OFF_MBAR 8
#define OFF_SA 1024
#define OFF_SB (1024 + S_STAGES * STG_BYTES)
#define SMEM_TC (1024 + 2 * S_STAGES * STG_BYTES)   // 132096
#define IDESC_TF32 ((1u << 4) | (2u << 7) | (2u << 10) | (16u << 17) | (8u << 24))

// single dynamic-shared declaration for the whole TU
extern __shared__ float dynsmem[];

// ---------------- scratch (device globals) ----------------
// All GEMM operands stored with K-axis interleave: within each 32-chunk,
// logical k stored at (k&3)*8 + (k>>2).  Dot products over a chunk are
// permutation-invariant when BOTH operands share the layout.
__device__ __align__(16) float g_Wg0t[(size_t)ND * HD];    // [n][k'] W_hh part (tf32)
__device__ __align__(16) float g_Wgt [(size_t)ND * HD];    // [n][k'] folded weight (tf32)
__device__ __align__(16) float g_WihI[(size_t)ND * OD];    // [n][o'] W_ih (tf32)
__device__ __align__(16) float g_WoutR[(size_t)OD * HD];   // [o][k'] Wout (tf32)
__device__ __align__(16) float g_WoutT[(size_t)HD * OD];   // [k][o'] Wout^T (tf32)
__device__ __align__(16) float g_b0[ND];
__device__ __align__(16) float g_bg[ND];
__device__ __align__(16) float g_h0[(size_t)BD * HD];      // [b][k'] tf32
__device__ __align__(16) float g_c [(size_t)BD * HD];      // [b][k'] fp32 cell state
__device__ __align__(16) float g_H [(size_t)TT * BD * HD]; // [t][b][k'] tf32

// ---------------- helpers ----------------
__device__ __forceinline__ int permK(int k) {
    return (k & ~31) + ((k & 3) << 3) + ((k >> 2) & 7);
}
__device__ __forceinline__ float to_tf32(float x) {
    unsigned u;
    asm("cvt.rna.tf32.f32 %0, %1;" : "=r"(u) : "f"(x));
    return __uint_as_float(u);
}
__device__ __forceinline__ float fsigmoid(float x) { return 1.0f / (1.0f + __expf(-x)); }
__device__ __forceinline__ float ftanh(float x) {
    float e = __expf(2.0f * x);
    return 1.0f - 2.0f / (e + 1.0f);
}
__device__ __forceinline__ void cp_a16(float* d, const float* s) {
    unsigned a = (unsigned)__cvta_generic_to_shared(d);
    asm volatile("cp.async.cg.shared.global [%0], [%1], 16;" :: "r"(a), "l"(s));
}

// ---------------- mma.sync mainloop: C(128x128) += A(128xK) * B(128xK)^T ----------------
// A stored [row][k'] (lda), B stored [col][k'] (ldb), both K-interleaved.
__device__ __forceinline__ void gemm_tile(
    const float* __restrict__ A, int lda,
    const float* __restrict__ B, int ldb,
    int m0, int n0, int kTiles,
    float (&acc)[4][4][4], float* sm)
{
    float* sA = sm;
    float* sB = sm + 3 * GSTG;
    const int tid = threadIdx.x;
    const int lane = tid & 31;
    const int wid = tid >> 5;
    const int wm = wid & 1, wn = wid >> 1;
    const int gid = lane >> 2, tig = lane & 3;

#define LOAD_STAGE(s, k0) do { \
        float* dA = sA + (s) * GSTG; \
        float* dB = sB + (s) * GSTG; \
        _Pragma("unroll") \
        for (int i = 0; i < 4; ++i) { \
            int slot = tid + i * 256; \
            int r = slot >> 3, cc = slot & 7; \
            cp_a16(dA + r * GP + cc * 4, A + (size_t)(m0 + r) * lda + (k0) + cc * 4); \
        } \
        _Pragma("unroll") \
        for (int i = 0; i < 4; ++i) { \
            int slot = tid + i * 256; \
            int r = slot >> 3, cc = slot & 7; \
            cp_a16(dB + r * GP + cc * 4, B + (size_t)(n0 + r) * ldb + (k0) + cc * 4); \
        } \
        asm volatile("cp.async.commit_group;" ::: "memory"); \
    } while (0)

    LOAD_STAGE(0, 0);
    LOAD_STAGE(1, 32);

    int cs = 0;        // compute stage
    int ls = 2;        // next load stage slot
    for (int kt = 0; kt < kTiles; ++kt) {
        if (kt + 1 < kTiles) asm volatile("cp.async.wait_group 1;" ::: "memory");
        else                 asm volatile("cp.async.wait_group 0;" ::: "memory");
        __syncthreads();
        if (kt + 2 < kTiles) {
            LOAD_STAGE(ls, (kt + 2) * 32);
            ls = (ls + 1 == 3) ? 0 : ls + 1;
        }

        const float* cA = sA + cs * GSTG;
        const float* cB = sB + cs * GSTG;
        cs = (cs + 1 == 3) ? 0 : cs + 1;

        #pragma unroll
        for (int h2 = 0; h2 < 2; ++h2) {
            float aw[8][4];
            float bw[4][4];
            #pragma unroll
            for (int mf = 0; mf < 4; ++mf)
                #pragma unroll
                for (int rh = 0; rh < 2; ++rh) {
                    int r = wm * 64 + mf * 16 + gid + rh * 8;
                    *(float4*)aw[mf * 2 + rh] = *(const float4*)&cA[r * GP + tig * 8 + h2 * 4];
                }
            #pragma unroll
            for (int nf = 0; nf < 4; ++nf) {
                int r = wn * 32 + nf * 8 + gid;
                *(float4*)bw[nf] = *(const float4*)&cB[r * GP + tig * 8 + h2 * 4];
            }
            #pragma unroll
            for (int ks2 = 0; ks2 < 2; ++ks2) {
                #pragma unroll
                for (int mf = 0; mf < 4; ++mf) {
                    unsigned a0 = __float_as_uint(aw[mf * 2][2 * ks2]);
                    unsigned a1 = __float_as_uint(aw[mf * 2 + 1][2 * ks2]);
                    unsigned a2 = __float_as_uint(aw[mf * 2][2 * ks2 + 1]);
                    unsigned a3 = __float_as_uint(aw[mf * 2 + 1][2 * ks2 + 1]);
                    #pragma unroll
                    for (int nf = 0; nf < 4; ++nf) {
                        unsigned b0 = __float_as_uint(bw[nf][2 * ks2]);
                        unsigned b1 = __float_as_uint(bw[nf][2 * ks2 + 1]);
                        asm volatile(
                            "mma.sync.aligned.m16n8k8.row.col.f32.tf32.tf32.f32 "
                            "{%0,%1,%2,%3}, {%4,%5,%6,%7}, {%8,%9}, {%0,%1,%2,%3};"
                            : "+f"(acc[mf][nf][0]), "+f"(acc[mf][nf][1]),
                              "+f"(acc[mf][nf][2]), "+f"(acc[mf][nf][3])
                            : "r"(a0), "r"(a1), "r"(a2), "r"(a3), "r"(b0), "r"(b1));
                    }
                }
            }
        }
    }
#undef LOAD_STAGE
}

// ---------------- setup kernels ----------------
// Column layout: n = (j>>3)*32 + g*8 + (j&7)  ->  j = ((n>>5)<<3)|(n&7), g = (n>>3)&3
__global__ void k_build_Wg0t(const float* __restrict__ Whh) {
    size_t idx = (size_t)blockIdx.x * blockDim.x + threadIdx.x;
    if (idx >= (size_t)ND * HD) return;
    int n = (int)(idx >> 10);
    int k = (int)(idx & (HD - 1));
    int j = ((n >> 5) << 3) | (n & 7), g = (n >> 3) & 3;
    g_Wg0t[(size_t)n * HD + permK(k)] = to_tf32(Whh[(size_t)(g * HD + j) * HD + k]);
}
__global__ void k_build_WihI(const float* __restrict__ Wih) {
    size_t idx = (size_t)blockIdx.x * blockDim.x + threadIdx.x;
    if (idx >= (size_t)ND * OD) return;
    int n = (int)(idx >> 8);
    int o = (int)(idx & (OD - 1));
    int j = ((n >> 5) << 3) | (n & 7), g = (n >> 3) & 3;
    g_WihI[(size_t)n * OD + permK(o)] = to_tf32(Wih[(size_t)(g * HD + j) * OD + o]);
}
__global__ void k_build_Wout2(const float* __restrict__ Wout) {
    size_t idx = (size_t)blockIdx.x * blockDim.x + threadIdx.x;
    if (idx >= (size_t)OD * HD) return;
    int o = (int)(idx >> 10);
    int k = (int)(idx & (HD - 1));
    float v = to_tf32(Wout[idx]);
    g_WoutR[(size_t)o * HD + permK(k)] = v;          // [o][k']
    g_WoutT[(size_t)k * OD + permK(o)] = v;          // [k][o']
}
__global__ void k_bias(const float* __restrict__ Wih, const float* __restrict__ bih,
                       const float* __restrict__ bhh, const float* __restrict__ bout) {
    int warp = (blockIdx.x * blockDim.x + threadIdx.x) >> 5;
    int lane = threadIdx.x & 31;
    if (warp >= ND) return;
    int n = warp;
    int j = ((n >> 5) << 3) | (n & 7), g = (n >> 3) & 3;
    int np = g * HD + j;
    float acc = 0.f;
    const float* wr = Wih + (size_t)np * OD;
    for (int o = lane; o < OD; o += 32) acc += wr[o] * bout[o];
    #pragma unroll
    for (int off = 16; off; off >>= 1) acc += __shfl_xor_sync(0xFFFFFFFFu, acc, off);
    if (lane == 0) {
        float b0 = bih[np] + bhh[np];
        g_b0[n] = b0;
        g_bg[n] = b0 + acc;
    }
}
__global__ void k_h0c(const float* __restrict__ enc) {
    size_t idx = (size_t)blockIdx.x * blockDim.x + threadIdx.x;
    if (idx >= (size_t)BD * HD) return;
    int b = (int)(idx >> 10);
    int k = (int)(idx & (HD - 1));
    g_h0[(size_t)b * HD + permK(k)] = to_tf32(enc[idx]);
    g_c[idx] = 0.0f;
}
// Wgt[n][k'] = tf32( Wg0t[n][k'] + (Wih*Wout)[np][k] )
__global__ __launch_bounds__(256, 1) void k_build_Wgt() {
    float* smem = dynsmem;
    const int m0 = blockIdx.y * 128;   // gate rows
    const int n0 = blockIdx.x * 128;   // k cols (logical)
    float acc[4][4][4];
    #pragma unroll
    for (int a = 0; a < 4; ++a)
        #pragma unroll
        for (int b = 0; b < 4; ++b)
            #pragma unroll
            for (int c = 0; c < 4; ++c) acc[a][b][c] = 0.f;
    gemm_tile(g_WihI, OD, g_WoutT, OD, m0, n0, OD / 32, acc, smem);

    const int tid = threadIdx.x, lane = tid & 31, wid = tid >> 5;
    const int wm = wid & 1, wn = wid >> 1, gid = lane >> 2, tig = lane & 3;
    #pragma unroll
    for (int mf = 0; mf < 4; ++mf)
        #pragma unroll
        for (int nf = 0; nf < 4; ++nf) {
            int c0 = n0 + wn * 32 + nf * 8 + 2 * tig;
            #pragma unroll
            for (int half = 0; half < 2; ++half) {
                int row = m0 + wm * 64 + mf * 16 + gid + half * 8;
                #pragma unroll
                for (int dd = 0; dd < 2; ++dd) {
                    size_t p = (size_t)row * HD + permK(c0 + dd);
                    g_Wgt[p] = to_tf32(g_Wg0t[p] + acc[mf][nf][half * 2 + dd]);
                }
            }
        }
}

// ---------------- tcgen05 machinery (compiled only for arch-specific targets) ----------
#if defined(__CUDA_ARCH_SPECIFIC__)
__device__ __forceinline__ uint32_t smem_u32(const void* p) {
    uint32_t a;
    asm("{ .reg .u64 t; cvta.to.shared.u64 t, %1; cvt.u32.u64 %0, t; }" : "=r"(a) : "l"(p));
    return a;
}
__device__ __forceinline__ uint32_t elect_one() {
    uint32_t pred;
    asm volatile("{\n\t.reg .pred p;\n\telect.sync _|p, 0xFFFFFFFF;\n\tselp.b32 %0, 1, 0, p;\n\t}" : "=r"(pred));
    return pred;
}
#define MBAR_INIT(addr, cnt) \
    asm volatile("mbarrier.init.shared.b64 [%0], %1;" :: "r"(addr), "r"((uint32_t)(cnt)) : "memory")
#define MBAR_WAIT(addr, par) do { \
    uint32_t _m = (addr), _p = (par), _d; \
    asm volatile("{\n\t.reg .pred p;\n\t" \
        "mbarrier.try_wait.parity.acquire.cta.shared::cta.b64 p, [%1], %2;\n\t" \
        "selp.b32 %0, 1, 0, p;\n\t}" : "=r"(_d) : "r"(_m), "r"(_p) : "memory"); \
    if (!_d) { \
        asm volatile("{\n\t.reg .pred P1;\n\t" \
            "WL_%=:\n\t" \
            "mbarrier.try_wait.parity.acquire.cta.shared::cta.b64 P1, [%0], %1, 0x989680;\n\t" \
            "@P1 bra.uni WD_%=;\n\t" \
            "bra.uni WL_%=;\n\t" \
            "WD_%=:\n\t}" :: "r"(_m), "r"(_p) : "memory"); \
    } \
} while (0)
#define TC_ALLOC(smaddr, n) \
    asm volatile("tcgen05.alloc.cta_group::1.sync.aligned.shared::cta.b32 [%0], %1;" \
        :: "r"(smaddr), "r"((uint32_t)(n)) : "memory")
#define TC_RELINQ() asm volatile("tcgen05.relinquish_alloc_permit.cta_group::1.sync.aligned;")
#define TC_DEALLOC(tm, n) \
    asm volatile("tcgen05.dealloc.cta_group::1.sync.aligned.b32 %0, %1;" :: "r"(tm), "r"((uint32_t)(n)))
#define TC_COMMIT(mbar) \
    asm volatile("tcgen05.commit.cta_group::1.mbarrier::arrive::one.shared::cluster.b64 [%0];" \
        :: "r"(mbar) : "memory")
#define TC_FENCE_AFTER() asm volatile("tcgen05.fence::after_thread_sync;" ::: "memory")
#define TC_FENCE_BEFORE() asm volatile("tcgen05.fence::before_thread_sync;" ::: "memory")
#define TC_WAIT_LD() asm volatile("tcgen05.wait::ld.sync.aligned;" ::: "memory")
#define TC_LD_X32(r, tm) \
    asm volatile("tcgen05.ld.sync.aligned.32x32b.x32.b32 " \
        "{%0, %1, %2, %3, %4, %5, %6, %7, %8, %9, %10, %11, %12, %13, %14, %15, " \
        " %16, %17, %18, %19, %20, %21, %22, %23, %24, %25, %26, %27, %28, %29, %30, %31}, [%32];" \
        : "=r"((r)[0]),  "=r"((r)[1]),  "=r"((r)[2]),  "=r"((r)[3]), \
          "=r"((r)[4]),  "=r"((r)[5]),  "=r"((r)[6]),  "=r"((r)[7]), \
          "=r"((r)[8]),  "=r"((r)[9]),  "=r"((r)[10]), "=r"((r)[11]), \
          "=r"((r)[12]), "=r"((r)[13]), "=r"((r)[14]), "=r"((r)[15]), \
          "=r"((r)[16]), "=r"((r)[17]), "=r"((r)[18]), "=r"((r)[19]), \
          "=r"((r)[20]), "=r"((r)[21]), "=r"((r)[22]), "=r"((r)[23]), \
          "=r"((r)[24]), "=r"((r)[25]), "=r"((r)[26]), "=r"((r)[27]), \
          "=r"((r)[28]), "=r"((r)[29]), "=r"((r)[30]), "=r"((r)[31]) \
        : "r"(tm))
__device__ __forceinline__ uint64_t make_desc_sw128(uint32_t addr) {
    const uint64_t base =
        (uint64_t(2) << 61) | (uint64_t(1) << 46) | (uint64_t(64) << 32) | (uint64_t(1) << 16);
    return base | ((uint64_t)(addr >> 4) & 0x3FFF);
}
__device__ __forceinline__ void mma_tf32_ss(uint32_t d_tmem, uint64_t a_desc, uint64_t b_desc,
                                            uint32_t en) {
    asm volatile(
        "{\n\t.reg .pred p;\n\tsetp.ne.u32 p, %5, 0;\n\t"
        "tcgen05.mma.cta_group::1.kind::tf32 [%0], %1, %2, %3, {%4, %4, %4, %4}, p;\n\t}"
        :: "r"(d_tmem), "l"(a_desc), "l"(b_desc), "r"(IDESC_TF32), "r"(0u), "r"(en)
        : "memory");
}
__device__ __forceinline__ void tc_load_stage(char* smem, int s,
    const float* __restrict__ A, const float* __restrict__ Bm,
    int m0, int n0, int k0, int tid)
{
    char* sA = smem + OFF_SA + s * STG_BYTES;
    char* sB = smem + OFF_SB + s * STG_BYTES;
    #pragma unroll
    for (int i = 0; i < 4; ++i) {
        int ch = tid + i * 256;
        int r = ch >> 3, cc = ch & 7;
        int sw = (r * 128 + cc * 16) ^ ((r & 7) << 4);
        cp_a16((float*)(sA + sw), A + (size_t)(m0 + r) * HD + k0 + cc * 4);
    }
    #pragma unroll
    for (int i = 0; i < 4; ++i) {
        int ch = tid + i * 256;
        int r = ch >> 3, cc = ch & 7;
        int sw = (r * 128 + cc * 16) ^ ((r & 7) << 4);
        cp_a16((float*)(sB + sw), Bm + (size_t)(n0 + r) * HD + k0 + cc * 4);
    }
}
#endif  // __CUDA_ARCH_SPECIFIC__

// ---------------- recurrence step (one kernel, arch-selected body) ----------------
__global__ __launch_bounds__(256, 1) void k_step(int t) {
    const float* hprev = (t == 0) ? g_h0 : (g_H + (size_t)(t - 1) * BD * HD);
    const float* W     = (t == 0) ? g_Wg0t : g_Wgt;
    const float* bias  = (t == 0) ? g_b0 : g_bg;
    float* hout = g_H + (size_t)t * BD * HD;
    const int n0 = blockIdx.x * 128;   // gate cols
    const int m0 = blockIdx.y * 128;   // batch rows
    const int tid = threadIdx.x, wid = tid >> 5, lane = tid & 31;

#if defined(__CUDA_ARCH_SPECIFIC__)
    // ---------- tcgen05 path ----------
    char* smem = (char*)dynsmem;
    const uint32_t smb = smem_u32(smem);

    if (wid == 0) TC_ALLOC(smb + OFF_TMEMPTR, 128);
    if (tid == 0) {
        #pragma unroll
        for (int s = 0; s < S_STAGES; ++s) MBAR_INIT(smb + OFF_MBAR + s * 8, 1);
        MBAR_INIT(smb + OFF_MBAR + S_STAGES * 8, 1);
    }
    __syncthreads();
    uint32_t tmem;
    asm volatile("ld.shared.b32 %0, [%1];" : "=r"(tmem) : "r"(smb + OFF_TMEMPTR));

    #pragma unroll
    for (int p = 0; p < S_STAGES - 1; ++p) {
        tc_load_stage(smem, p, hprev, W, m0, n0, p * 32, tid);
        asm volatile("cp.async.commit_group;" ::: "memory");
    }
    for (int kt = 0; kt < 32; ++kt) {
        const int q = kt + S_STAGES - 1;
        if (q < 32) {
            const int r = q >> 2;
            if (r >= 1) MBAR_WAIT(smb + OFF_MBAR + (q & 3) * 8, (r - 1) & 1);
            tc_load_stage(smem, q & 3, hprev, W, m0, n0, q * 32, tid);
        }
        asm volatile("cp.async.commit_group;" ::: "memory");
        asm volatile("cp.async.wait_group %0;" :: "n"(S_STAGES - 1) : "memory");
        asm volatile("fence.proxy.async.shared::cta;" ::: "memory");
        __syncthreads();
        if (wid == 0 && elect_one()) {
            const int s = kt & 3;
            uint64_t ad = make_desc_sw128(smb + OFF_SA + s * STG_BYTES);
            uint64_t bd = make_desc_sw128(smb + OFF_SB + s * STG_BYTES);
            #pragma unroll
            for (int k8 = 0; k8 < 4; ++k8)
                mma_tf32_ss(tmem, ad + k8 * 2, bd + k8 * 2, (kt > 0 || k8 > 0) ? 1u : 0u);
            TC_COMMIT(smb + OFF_MBAR + s * 8);
        }
    }
    if (wid == 0 && elect_one()) TC_COMMIT(smb + OFF_MBAR + S_STAGES * 8);
    MBAR_WAIT(smb + OFF_MBAR + S_STAGES * 8, 0);
    TC_FENCE_AFTER();

    {   // epilogue: 8 warps, sub = wid&3 rows, half = wid>>2 selects col half
        const int sub = wid & 3, hf = wid >> 2;
        const int row = m0 + sub * 32 + lane;
        #pragma unroll
        for (int cb = 0; cb < 2; ++cb) {
            uint32_t regs[32];
            const int colb = hf * 64 + cb * 32;
            TC_LD_X32(regs, tmem + colb);
            TC_WAIT_LD();
            const int nb = n0 + colb;
            const int jb = nb >> 2;
            #pragma unroll
            for (int u = 0; u < 8; ++u) {
                float ig = fsigmoid(__uint_as_float(regs[u])      + bias[nb + u]);
                float fg = fsigmoid(__uint_as_float(regs[8 + u])  + bias[nb + 8 + u]);
                float gg = ftanh  (__uint_as_float(regs[16 + u]) + bias[nb + 16 + u]);
                float og = fsigmoid(__uint_as_float(regs[24 + u]) + bias[nb + 24 + u]);
                int j = jb + u;
                size_t p = (size_t)row * HD + permK(j);
                float cn = fg * g_c[p] + ig * gg;
                g_c[p] = cn;
                hout[p] = to_tf32(og * ftanh(cn));
            }
        }
    }
    TC_FENCE_BEFORE();
    __syncthreads();
    if (wid == 0) { TC_RELINQ(); TC_DEALLOC(tmem, 128); }

#else
    // ---------- mma.sync fallback (plain sm_103) ----------
    float* smem = dynsmem;
    const int wm = wid & 1, wn = wid >> 1, gid = lane >> 2, tig = lane & 3;

    float acc[4][4][4];
    #pragma unroll
    for (int a = 0; a < 4; ++a)
        #pragma unroll
        for (int b = 0; b < 4; ++b)
            #pragma unroll
            for (int c = 0; c < 4; ++c) acc[a][b][c] = 0.f;
    gemm_tile(hprev, HD, W, HD, m0, n0, HD / 32, acc, smem);

    // cell epilogue fully in registers: acc[mf][gate][half*2 + (u&1)]
    const int nb = n0 + wn * 32;
    const int jb = nb >> 2;           // first unit of this warp's 8-unit block
    const int ub = 2 * tig;
    float bI[2], bF[2], bG[2], bO[2];
    #pragma unroll
    for (int uu = 0; uu < 2; ++uu) {
        bI[uu] = bias[nb +       ub + uu];
        bF[uu] = bias[nb +  8 +  ub + uu];
        bG[uu] = bias[nb + 16 +  ub + uu];
        bO[uu] = bias[nb + 24 +  ub + uu];
    }
    #pragma unroll
    for (int mf = 0; mf < 4; ++mf)
        #pragma unroll
        for (int half = 0; half < 2; ++half) {
            const int b = m0 + wm * 64 + mf * 16 + gid + half * 8;
            #pragma unroll
            for (int uu = 0; uu < 2; ++uu) {
                const int j = jb + ub + uu;
                size_t p = (size_t)b * HD + permK(j);
                float ig = fsigmoid(acc[mf][0][half * 2 + uu] + bI[uu]);
                float fg = fsigmoid(acc[mf][1][half * 2 + uu] + bF[uu]);
                float gg = ftanh  (acc[mf][2][half * 2 + uu] + bG[uu]);
                float og = fsigmoid(acc[mf][3][half * 2 + uu] + bO[uu]);
                float cn = fg * g_c[p] + ig * gg;
                g_c[p] = cn;
                hout[p] = to_tf32(og * ftanh(cn));
            }
        }
#endif
}

// ---------------- final prediction GEMM: (T*B, O) = H_all @ Wout^T + b_out ----------------
__global__ __launch_bounds__(256, 1) void k_pred(const float* __restrict__ bout,
                                                 float* __restrict__ out) {
    float* smem = dynsmem;
    const int m0 = blockIdx.y * 128;
    const int n0 = blockIdx.x * 128;
    float acc[4][4][4];
    #pragma unroll
    for (int a = 0; a < 4; ++a)
        #pragma unroll
        for (int b = 0; b < 4; ++b)
            #pragma unroll
            for (int c = 0; c < 4; ++c) acc[a][b][c] = 0.f;
    gemm_tile(g_H, HD, g_WoutR, HD, m0, n0, HD / 32, acc, smem);

    const int tid = threadIdx.x, lane = tid & 31, wid = tid >> 5;
    const int wm = wid & 1, wn = wid >> 1, gid = lane >> 2, tig = lane & 3;
    #pragma unroll
    for (int mf = 0; mf < 4; ++mf)
        #pragma unroll
        for (int nf = 0; nf < 4; ++nf) {
            int c = wn * 32 + nf * 8 + 2 * tig;
            int o = n0 + c;
            float b0v = bout[o], b1v = bout[o + 1];
            #pragma unroll
            for (int half = 0; half < 2; ++half) {
                int m = m0 + wm * 64 + mf * 16 + gid + half * 8;
                int t = m >> 9;
                int b = m & 511;
                float2 v;
                v.x = acc[mf][nf][half * 2 + 0] + b0v;
                v.y = acc[mf][nf][half * 2 + 1] + b1v;
                *(float2*)&out[((size_t)b * TT + t) * OD + o] = v;
            }
        }
}

// ---------------- host launcher ----------------
extern "C" void kernel_launch(void* const* d_in, const int* in_sizes, int n_in,
                              void* d_out, int out_size) {
    const float* enc  = (const float*)d_in[0];
    const float* Wih  = (const float*)d_in[2];
    const float* Whh  = (const float*)d_in[3];
    const float* bih  = (const float*)d_in[4];
    const float* bhh  = (const float*)d_in[5];
    const float* Wout = (const float*)d_in[6];
    const float* bout = (const float*)d_in[7];
    float* out = (float*)d_out;

    const int stepSmem = (SMEM_TC > GEMM_SMEM) ? SMEM_TC : GEMM_SMEM;
    cudaFuncSetAttribute(k_build_Wgt, cudaFuncAttributeMaxDynamicSharedMemorySize, GEMM_SMEM);
    cudaFuncSetAttribute(k_pred,      cudaFuncAttributeMaxDynamicSharedMemorySize, GEMM_SMEM);
    cudaFuncSetAttribute(k_step,      cudaFuncAttributeMaxDynamicSharedMemorySize, stepSmem);

    k_build_Wg0t <<<(ND * HD + 255) / 256, 256>>>(Whh);
    k_build_WihI <<<(ND * OD + 255) / 256, 256>>>(Wih);
    k_build_Wout2<<<(OD * HD + 255) / 256, 256>>>(Wout);
    k_bias       <<<(ND * 32 + 255) / 256, 256>>>(Wih, bih, bhh, bout);
    k_h0c        <<<(BD * HD + 255) / 256, 256>>>(enc);

    {
        dim3 g(HD / 128, ND / 128);        // 8 x 32
        k_build_Wgt<<<g, 256, GEMM_SMEM>>>();
    }
    {
        dim3 g(ND / 128, BD / 128);        // 32 x 4
        for (int t = 0; t < TT; ++t) k_step<<<g, 256, stepSmem>>>(t);
    }
    {
        dim3 g(OD / 128, (TT * BD) / 128); // 2 x 512
        k_pred<<<g, 256, GEMM_SMEM>>>(bout, out);
    }
}